// round 16
// baseline (speedup 1.0000x reference)
#include <cuda_runtime.h>
#include <cuda_fp16.h>
#include <cstdint>

// dims: B=64, T=512, D=U=1024, 4U=4096
#define NCTA 128

// ---------------- scratch (__device__ globals) -----------------------------
__device__ __align__(16) __half g_xf[(size_t)32768 * 1024];    // x fp16, rows m=t*64+b
__device__ __align__(16) __half g_wxf[(size_t)4096 * 1024];    // Wx fp16 (permuted rows)
__device__ __align__(16) __half g_whfh[(size_t)4096 * 1024];   // Wh fp16 (permuted rows)
// write-once h history (fp16): step t reads [t], writes [t+1]
__device__ __align__(16) __half g_htf[513][64 * 1024];
__device__ int g_cnt[512];                              // per-step arrival counters

// ---------------- helpers --------------------------------------------------
__device__ __forceinline__ uint32_t smem_u32(const void* p) {
    uint32_t a;
    asm("{ .reg .u64 t; cvta.to.shared.u64 t, %1; cvt.u32.u64 %0, t; }" : "=r"(a) : "l"(p));
    return a;
}
__device__ __forceinline__ void cp16(uint32_t saddr, const void* g) {
    asm volatile("cp.async.cg.shared.global [%0], [%1], 16;" :: "r"(saddr), "l"(g) : "memory");
}
#define CP_COMMIT() asm volatile("cp.async.commit_group;" ::: "memory")
#define CP_WAIT1()  asm volatile("cp.async.wait_group 1;" ::: "memory")
#define CP_WAIT0()  asm volatile("cp.async.wait_group 0;" ::: "memory")

__device__ __forceinline__ void ldsm4(uint32_t* r, uint32_t addr) {
    asm volatile("ldmatrix.sync.aligned.m8n8.x4.shared.b16 {%0,%1,%2,%3}, [%4];"
        : "=r"(r[0]), "=r"(r[1]), "=r"(r[2]), "=r"(r[3]) : "r"(addr));
}
__device__ __forceinline__ void ldsm2(uint32_t* r, uint32_t addr) {
    asm volatile("ldmatrix.sync.aligned.m8n8.x2.shared.b16 {%0,%1}, [%2];"
        : "=r"(r[0]), "=r"(r[1]) : "r"(addr));
}
__device__ __forceinline__ void mma_f16(float* c, const uint32_t* a, uint32_t b0, uint32_t b1) {
    asm volatile("mma.sync.aligned.m16n8k16.row.col.f32.f16.f16.f32 "
        "{%0,%1,%2,%3}, {%4,%5,%6,%7}, {%8,%9}, {%0,%1,%2,%3};"
        : "+f"(c[0]), "+f"(c[1]), "+f"(c[2]), "+f"(c[3])
        : "r"(a[0]), "r"(a[1]), "r"(a[2]), "r"(a[3]), "r"(b0), "r"(b1));
}
__device__ __forceinline__ void red_release(int* p) {
    asm volatile("red.release.gpu.global.add.s32 [%0], 1;" :: "l"(p) : "memory");
}
__device__ __forceinline__ int ld_acq(const int* p) {
    int v; asm volatile("ld.acquire.gpu.global.b32 %0, [%1];" : "=r"(v) : "l"(p) : "memory"); return v;
}
// column permutation: p = j*32 + g*8 + uu  <->  gcol = g*1024 + j*8 + uu
__device__ __forceinline__ int gcol_of(int p) {
    return ((p >> 3) & 3) * 1024 + (p >> 5) * 8 + (p & 7);
}
// smem tile: rows of 128B (64 fp16), 16B chunks xor-swizzled by row
__device__ __forceinline__ uint32_t tadr(int row, int ch) {
    return (uint32_t)(row * 128 + ((ch ^ (row & 7)) << 4));
}

// ---------------- init -----------------------------------------------------
__global__ void init_kernel() {
    int i = blockIdx.x * 256 + threadIdx.x;
    if (i < 8192) ((uint4*)g_htf[0])[i] = make_uint4(0, 0, 0, 0);
    if (i < 512) g_cnt[i] = 0;
}

// ---------------- packers --------------------------------------------------
__global__ void __launch_bounds__(256) pack_x_kernel(const float* __restrict__ x) {
    int u = blockIdx.x * 256 + threadIdx.x;           // 4194304
    int k8 = u & 127, m = u >> 7;
    int t = m >> 6, b = m & 63;
    const float* s = x + ((size_t)(b * 512 + t)) * 1024 + k8 * 8;
    float4 v0 = *(const float4*)s, v1 = *(const float4*)(s + 4);
    float v[8] = {v0.x, v0.y, v0.z, v0.w, v1.x, v1.y, v1.z, v1.w};
    __half hb[8];
#pragma unroll
    for (int i = 0; i < 8; i++) hb[i] = __float2half_rn(v[i]);
    *(uint4*)(g_xf + (size_t)m * 1024 + k8 * 8) = *(uint4*)hb;
}

__global__ void __launch_bounds__(256) pack_w_kernel(const float* __restrict__ W, int mode) {
    __shared__ float s[32][33];
    int p0 = blockIdx.x * 32, k0 = blockIdx.y * 32;
    int tid = threadIdx.x;
#pragma unroll
    for (int i = 0; i < 4; i++) {
        int idx = tid + i * 256;
        int kk = idx >> 5, pp = idx & 31;
        s[kk][pp] = W[(size_t)(k0 + kk) * 4096 + gcol_of(p0 + pp)];
    }
    __syncthreads();
    if (tid < 128) {
        int pp = tid >> 2, k8 = (tid & 3) * 8;
        size_t o = (size_t)(p0 + pp) * 1024 + k0 + k8;
        __half hb[8];
#pragma unroll
        for (int i = 0; i < 8; i++) hb[i] = __float2half_rn(s[k8 + i][pp]);
        *(uint4*)((mode ? g_whfh : g_wxf) + o) = *(uint4*)hb;
    }
}

// ---------------- fused persistent LSTM ------------------------------------
// smem: A stages 2x32KB at 0/32768 (shared by x- and h-phase, serial)
//       WH 64KB at 65536 | WX 64KB at 131072.  Total 192KB.
#define WH_OFF 65536u
#define WX_OFF 131072u
#define ST_SMEM 196608

// load A chunk: 64 rows x 256 k fp16 = 32KB; 64k sub-blocks of 8KB.
__device__ __forceinline__ void st_load_A(uint32_t sb, uint32_t stage_off, int tid,
                                          const __half* src, int k0) {
    uint32_t st = sb + stage_off;
#pragma unroll
    for (int rep = 0; rep < 8; rep++) {
        int idx = tid + rep * 256;                 // 0..2047
        int c = idx >> 9, r = idx & 511;
        int row = r >> 3, ch = r & 7;
        cp16(st + c * 8192 + tadr(row, ch),
             src + (size_t)row * 1024 + k0 + c * 64 + ch * 8);
    }
}

// compute one 256k chunk: A in stage, B resident at w_off (16KB per chunk).
__device__ __forceinline__ void st_compute(uint32_t sb, uint32_t stage_off, uint32_t w_off,
                                           int kt, int lane,
                                           int m_off, int n_off, float C[2][4]) {
    uint32_t st = sb + stage_off;
    uint32_t wh = sb + w_off + (uint32_t)kt * 16384;
    int r15 = lane & 15, kh = lane >> 4;
#pragma unroll
    for (int sub = 0; sub < 4; sub++) {
        uint32_t Ab = st + sub * 8192;
        uint32_t Bb = wh + sub * 4096;
#pragma unroll
        for (int ks = 0; ks < 4; ks++) {
            int ch = ks * 2 + kh;
            uint32_t aH[8], bH[2];
#pragma unroll
            for (int mt = 0; mt < 2; mt++)
                ldsm4(aH + mt * 4, Ab + tadr(m_off + mt * 16 + r15, ch));
            ldsm2(bH, Bb + tadr(n_off + (r15 & 7), ks * 2 + (r15 >> 3)));
#pragma unroll
            for (int mt = 0; mt < 2; mt++)
                mma_f16(C[mt], aH + mt * 4, bH[0], bH[1]);
        }
    }
}

__global__ void __launch_bounds__(256, 1) step_persist(float* __restrict__ y,
                                                       const float* __restrict__ bias) {
    extern __shared__ __align__(16) unsigned char sm[];
    uint32_t sb = smem_u32(sm);
    const int tid = threadIdx.x, lane = tid & 31, w = tid >> 5;
    const int j = blockIdx.x, p0 = j * 32;
    const int m_off = (w & 1) * 32, n_off = (w >> 1) * 8;

    // ---- preload Wh + Wx slices (32 p-rows x 1024 k fp16 = 64KB each) -----
#pragma unroll
    for (int rep = 0; rep < 16; rep++) {
        int idx = tid + rep * 256;                 // 0..4095
        int kb = idx >> 8;                         // 64k-block 0..15
        int r = idx & 255;
        int row = r >> 3, ch = r & 7;
        size_t go = (size_t)(p0 + row) * 1024 + kb * 64 + ch * 8;
        cp16(sb + WH_OFF + kb * 4096 + tadr(row, ch), g_whfh + go);
        cp16(sb + WX_OFF + kb * 4096 + tadr(row, ch), g_wxf + go);
    }
    CP_COMMIT(); CP_WAIT0();
    __syncthreads();

    // per-thread persistent state
    float creg[2] = {0.0f, 0.0f};                  // cell state (b, u) fixed per thread
    const int er = lane >> 2, ec2 = (lane & 3) * 2;
    const float bv0 = bias[gcol_of(p0 + n_off + ec2)];
    const float bv1 = bias[gcol_of(p0 + n_off + ec2 + 1)];

#pragma unroll 1
    for (int t = 0; t < 512; t++) {
        // ===== x-phase: Cx = x_t @ Wx (independent of barrier) =============
        const __half* xf = g_xf + (size_t)t * 65536;
        float Cx[2][4];
#pragma unroll
        for (int i = 0; i < 2; i++)
#pragma unroll
            for (int q = 0; q < 4; q++) Cx[i][q] = 0.0f;

        st_load_A(sb, 0, tid, xf, 0);       CP_COMMIT();
        st_load_A(sb, 32768, tid, xf, 256); CP_COMMIT();
#pragma unroll 1
        for (int kt = 0; kt < 4; kt++) {
            if (kt < 3) { CP_WAIT1(); } else { CP_WAIT0(); }
            __syncthreads();
            st_compute(sb, (uint32_t)(kt & 1) * 32768, WX_OFF, kt, lane, m_off, n_off, Cx);
            __syncthreads();
            if (kt + 2 < 4) { st_load_A(sb, (uint32_t)(kt & 1) * 32768, tid, xf, (kt + 2) * 256); CP_COMMIT(); }
        }

        // ===== barrier wait: h_t must be complete ==========================
        if (t > 0) {
            if (tid == 0) {
                while (ld_acq(&g_cnt[t - 1]) < NCTA) { }
            }
        }
        __syncthreads();

        // ===== h-phase: Ch = h_t @ Wh ======================================
        const __half* hf = g_htf[t];
        float Ch[2][4];
#pragma unroll
        for (int i = 0; i < 2; i++)
#pragma unroll
            for (int q = 0; q < 4; q++) Ch[i][q] = 0.0f;

        st_load_A(sb, 0, tid, hf, 0);       CP_COMMIT();
        st_load_A(sb, 32768, tid, hf, 256); CP_COMMIT();
#pragma unroll 1
        for (int kt = 0; kt < 4; kt++) {
            if (kt < 3) { CP_WAIT1(); } else { CP_WAIT0(); }
            __syncthreads();
            st_compute(sb, (uint32_t)(kt & 1) * 32768, WH_OFF, kt, lane, m_off, n_off, Ch);
            __syncthreads();
            if (kt + 2 < 4) { st_load_A(sb, (uint32_t)(kt & 1) * 32768, tid, hf, (kt + 2) * 256); CP_COMMIT(); }
        }

        // ===== merge frags -> Zs[n][b] (z = Ch + Cx + bias) ================
        float* Zs = (float*)sm;                    // [32][66], overlays stage 0
        {
#pragma unroll
            for (int mt = 0; mt < 2; mt++) {
                int m = m_off + mt * 16 + er;
                int n = n_off + ec2;
                Zs[n * 66 + m]           = Ch[mt][0] + Cx[mt][0] + bv0;
                Zs[(n + 1) * 66 + m]     = Ch[mt][1] + Cx[mt][1] + bv1;
                Zs[n * 66 + m + 8]       = Ch[mt][2] + Cx[mt][2] + bv0;
                Zs[(n + 1) * 66 + m + 8] = Ch[mt][3] + Cx[mt][3] + bv1;
            }
        }
        __syncthreads();

        // ===== fused gates; c in registers =================================
        {
            int b = tid >> 2, uq = tid & 3;
            float hv[2];
#pragma unroll
            for (int v = 0; v < 2; v++) {
                int uu = uq * 2 + v;
                float zi = Zs[uu * 66 + b];
                float zf = Zs[(8 + uu) * 66 + b];
                float zg = Zs[(16 + uu) * 66 + b];
                float zo = Zs[(24 + uu) * 66 + b];
                float ig = 1.0f / (1.0f + __expf(-zi));
                float fg = 1.0f / (1.0f + __expf(-zf));
                float gg = 2.0f / (1.0f + __expf(-2.0f * zg)) - 1.0f;
                float og = 1.0f / (1.0f + __expf(-zo));
                float cn = fg * creg[v] + ig * gg;
                creg[v] = cn;
                float th = 2.0f / (1.0f + __expf(-2.0f * cn)) - 1.0f;
                hv[v] = og * th;
            }
            *(float2*)&y[((size_t)b * 512 + t) * 1024 + j * 8 + uq * 2] =
                make_float2(hv[0], hv[1]);
            __half hf2[2];
            hf2[0] = __float2half_rn(hv[0]);
            hf2[1] = __float2half_rn(hv[1]);
            *(uint32_t*)(g_htf[t + 1] + (size_t)b * 1024 + j * 8 + uq * 2) = *(uint32_t*)hf2;
        }

        // ===== arrive: h_{t+1} visible -> release counter t ================
        __threadfence();
        __syncthreads();
        if (tid == 0) red_release(&g_cnt[t]);
    }
}

// ---------------------------------------------------------------------------
extern "C" void kernel_launch(void* const* d_in, const int* in_sizes, int n_in,
                              void* d_out, int out_size)
{
    const float* x  = (const float*)d_in[0];
    const float* Wx = (const float*)d_in[1];
    const float* Wh = (const float*)d_in[2];
    const float* b  = (const float*)d_in[3];
    float* y = (float*)d_out;

    cudaFuncSetAttribute(step_persist, cudaFuncAttributeMaxDynamicSharedMemorySize, ST_SMEM);

    init_kernel<<<64, 256>>>();
    pack_x_kernel<<<16384, 256>>>(x);
    pack_w_kernel<<<dim3(128, 32), 256>>>(Wx, 0);
    pack_w_kernel<<<dim3(128, 32), 256>>>(Wh, 1);
    step_persist<<<NCTA, 256, ST_SMEM>>>(y, b);
}

// round 17
// speedup vs baseline: 1.0858x; 1.0858x over previous
#include <cuda_runtime.h>
#include <cuda_fp16.h>
#include <cstdint>

// dims: B=64, T=512, D=U=1024, 4U=4096
#define NCTA 128

// ---------------- scratch (__device__ globals) -----------------------------
__device__ __align__(16) __half g_xf[(size_t)32768 * 1024];    // x fp16, rows m=t*64+b
__device__ __align__(16) __half g_wxf[(size_t)4096 * 1024];    // Wx fp16 (permuted rows)
__device__ __align__(16) __half g_whfh[(size_t)4096 * 1024];   // Wh fp16 (permuted rows)
// write-once h history (fp16): step t reads [t], writes [t+1]
__device__ __align__(16) __half g_htf[513][64 * 1024];
__device__ int g_cnt[512];                              // per-step arrival counters

// ---------------- helpers --------------------------------------------------
__device__ __forceinline__ uint32_t smem_u32(const void* p) {
    uint32_t a;
    asm("{ .reg .u64 t; cvta.to.shared.u64 t, %1; cvt.u32.u64 %0, t; }" : "=r"(a) : "l"(p));
    return a;
}
__device__ __forceinline__ void cp16(uint32_t saddr, const void* g) {
    asm volatile("cp.async.cg.shared.global [%0], [%1], 16;" :: "r"(saddr), "l"(g) : "memory");
}
#define CP_COMMIT() asm volatile("cp.async.commit_group;" ::: "memory")
#define CP_WAIT2()  asm volatile("cp.async.wait_group 2;" ::: "memory")
#define CP_WAIT1()  asm volatile("cp.async.wait_group 1;" ::: "memory")
#define CP_WAIT0()  asm volatile("cp.async.wait_group 0;" ::: "memory")

__device__ __forceinline__ void ldsm4(uint32_t* r, uint32_t addr) {
    asm volatile("ldmatrix.sync.aligned.m8n8.x4.shared.b16 {%0,%1,%2,%3}, [%4];"
        : "=r"(r[0]), "=r"(r[1]), "=r"(r[2]), "=r"(r[3]) : "r"(addr));
}
__device__ __forceinline__ void ldsm2(uint32_t* r, uint32_t addr) {
    asm volatile("ldmatrix.sync.aligned.m8n8.x2.shared.b16 {%0,%1}, [%2];"
        : "=r"(r[0]), "=r"(r[1]) : "r"(addr));
}
__device__ __forceinline__ void mma_f16(float* c, const uint32_t* a, uint32_t b0, uint32_t b1) {
    asm volatile("mma.sync.aligned.m16n8k16.row.col.f32.f16.f16.f32 "
        "{%0,%1,%2,%3}, {%4,%5,%6,%7}, {%8,%9}, {%0,%1,%2,%3};"
        : "+f"(c[0]), "+f"(c[1]), "+f"(c[2]), "+f"(c[3])
        : "r"(a[0]), "r"(a[1]), "r"(a[2]), "r"(a[3]), "r"(b0), "r"(b1));
}
__device__ __forceinline__ void red_release(int* p) {
    asm volatile("red.release.gpu.global.add.s32 [%0], 1;" :: "l"(p) : "memory");
}
__device__ __forceinline__ int ld_acq(const int* p) {
    int v; asm volatile("ld.acquire.gpu.global.b32 %0, [%1];" : "=r"(v) : "l"(p) : "memory"); return v;
}
// column permutation: p = j*32 + g*8 + uu  <->  gcol = g*1024 + j*8 + uu
__device__ __forceinline__ int gcol_of(int p) {
    return ((p >> 3) & 3) * 1024 + (p >> 5) * 8 + (p & 7);
}
// smem tile: rows of 128B (64 fp16), 16B chunks xor-swizzled by row
__device__ __forceinline__ uint32_t tadr(int row, int ch) {
    return (uint32_t)(row * 128 + ((ch ^ (row & 7)) << 4));
}

// ---------------- init -----------------------------------------------------
__global__ void init_kernel() {
    int i = blockIdx.x * 256 + threadIdx.x;
    if (i < 8192) ((uint4*)g_htf[0])[i] = make_uint4(0, 0, 0, 0);
    if (i < 512) g_cnt[i] = 0;
}

// ---------------- packers --------------------------------------------------
__global__ void __launch_bounds__(256) pack_x_kernel(const float* __restrict__ x) {
    int u = blockIdx.x * 256 + threadIdx.x;           // 4194304
    int k8 = u & 127, m = u >> 7;
    int t = m >> 6, b = m & 63;
    const float* s = x + ((size_t)(b * 512 + t)) * 1024 + k8 * 8;
    float4 v0 = *(const float4*)s, v1 = *(const float4*)(s + 4);
    float v[8] = {v0.x, v0.y, v0.z, v0.w, v1.x, v1.y, v1.z, v1.w};
    __half hb[8];
#pragma unroll
    for (int i = 0; i < 8; i++) hb[i] = __float2half_rn(v[i]);
    *(uint4*)(g_xf + (size_t)m * 1024 + k8 * 8) = *(uint4*)hb;
}

__global__ void __launch_bounds__(256) pack_w_kernel(const float* __restrict__ W, int mode) {
    __shared__ float s[32][33];
    int p0 = blockIdx.x * 32, k0 = blockIdx.y * 32;
    int tid = threadIdx.x;
#pragma unroll
    for (int i = 0; i < 4; i++) {
        int idx = tid + i * 256;
        int kk = idx >> 5, pp = idx & 31;
        s[kk][pp] = W[(size_t)(k0 + kk) * 4096 + gcol_of(p0 + pp)];
    }
    __syncthreads();
    if (tid < 128) {
        int pp = tid >> 2, k8 = (tid & 3) * 8;
        size_t o = (size_t)(p0 + pp) * 1024 + k0 + k8;
        __half hb[8];
#pragma unroll
        for (int i = 0; i < 8; i++) hb[i] = __float2half_rn(s[k8 + i][pp]);
        *(uint4*)((mode ? g_whfh : g_wxf) + o) = *(uint4*)hb;
    }
}

// ---------------- fused persistent LSTM ------------------------------------
// smem: A stages 3x32KB at 0/32768/65536 | WH 64KB at 98304 | WX 64KB at 163840.
// Total 229376 B.  Zs overlays stage 1 (safe: s1 last read two syncs earlier).
#define WH_OFF 98304u
#define WX_OFF 163840u
#define ZS_OFF 32768u
#define ST_SMEM 229376

// load A chunk: 64 rows x 256 k fp16 = 32KB; 64k sub-blocks of 8KB.
__device__ __forceinline__ void st_load_A(uint32_t sb, uint32_t stage_off, int tid,
                                          const __half* src, int k0) {
    uint32_t st = sb + stage_off;
#pragma unroll
    for (int rep = 0; rep < 8; rep++) {
        int idx = tid + rep * 256;                 // 0..2047
        int c = idx >> 9, r = idx & 511;
        int row = r >> 3, ch = r & 7;
        cp16(st + c * 8192 + tadr(row, ch),
             src + (size_t)row * 1024 + k0 + c * 64 + ch * 8);
    }
}

// compute one 256k chunk: A in stage, B resident at w_off (16KB per chunk kt).
__device__ __forceinline__ void st_compute(uint32_t sb, uint32_t stage_off, uint32_t w_off,
                                           int kt, int lane,
                                           int m_off, int n_off, float C[2][4]) {
    uint32_t st = sb + stage_off;
    uint32_t wh = sb + w_off + (uint32_t)kt * 16384;
    int r15 = lane & 15, kh = lane >> 4;
#pragma unroll
    for (int sub = 0; sub < 4; sub++) {
        uint32_t Ab = st + sub * 8192;
        uint32_t Bb = wh + sub * 4096;
#pragma unroll
        for (int ks = 0; ks < 4; ks++) {
            int ch = ks * 2 + kh;
            uint32_t aH[8], bH[2];
#pragma unroll
            for (int mt = 0; mt < 2; mt++)
                ldsm4(aH + mt * 4, Ab + tadr(m_off + mt * 16 + r15, ch));
            ldsm2(bH, Bb + tadr(n_off + (r15 & 7), ks * 2 + (r15 >> 3)));
#pragma unroll
            for (int mt = 0; mt < 2; mt++)
                mma_f16(C[mt], aH + mt * 4, bH[0], bH[1]);
        }
    }
}

// one GEMM phase (4 chunks, 3-stage pipeline, 1 sync per chunk).
// Chunk->stage: c0->s0, c1->s1, c2->s2, c3->s0 (issued at iter 1, after the
// sync that proves all warps finished computing c0 in s0).
__device__ __forceinline__ void st_phase(uint32_t sb, uint32_t w_off, int tid, int lane,
                                         int m_off, int n_off,
                                         const __half* src, float C[2][4]) {
    st_load_A(sb, 0,     tid, src, 0);   CP_COMMIT();
    st_load_A(sb, 32768, tid, src, 256); CP_COMMIT();
    st_load_A(sb, 65536, tid, src, 512); CP_COMMIT();
    CP_WAIT2(); __syncthreads();
    st_compute(sb, 0, w_off, 0, lane, m_off, n_off, C);
    CP_WAIT1(); __syncthreads();
    st_load_A(sb, 0, tid, src, 768); CP_COMMIT();
    st_compute(sb, 32768, w_off, 1, lane, m_off, n_off, C);
    CP_WAIT1(); __syncthreads();
    st_compute(sb, 65536, w_off, 2, lane, m_off, n_off, C);
    CP_WAIT0(); __syncthreads();
    st_compute(sb, 0, w_off, 3, lane, m_off, n_off, C);
}

__global__ void __launch_bounds__(256, 1) step_persist(float* __restrict__ y,
                                                       const float* __restrict__ bias) {
    extern __shared__ __align__(16) unsigned char sm[];
    uint32_t sb = smem_u32(sm);
    const int tid = threadIdx.x, lane = tid & 31, w = tid >> 5;
    const int j = blockIdx.x, p0 = j * 32;
    const int m_off = (w & 1) * 32, n_off = (w >> 1) * 8;

    // ---- preload Wh + Wx slices (32 p-rows x 1024 k fp16 = 64KB each) -----
#pragma unroll
    for (int rep = 0; rep < 16; rep++) {
        int idx = tid + rep * 256;                 // 0..4095
        int kb = idx >> 8;                         // 64k-block 0..15
        int r = idx & 255;
        int row = r >> 3, ch = r & 7;
        size_t go = (size_t)(p0 + row) * 1024 + kb * 64 + ch * 8;
        cp16(sb + WH_OFF + kb * 4096 + tadr(row, ch), g_whfh + go);
        cp16(sb + WX_OFF + kb * 4096 + tadr(row, ch), g_wxf + go);
    }
    CP_COMMIT(); CP_WAIT0();
    __syncthreads();

    // per-thread persistent state
    float creg[2] = {0.0f, 0.0f};                  // cell state (b, u) fixed per thread
    const int er = lane >> 2, ec2 = (lane & 3) * 2;
    const float bv0 = bias[gcol_of(p0 + n_off + ec2)];
    const float bv1 = bias[gcol_of(p0 + n_off + ec2 + 1)];

#pragma unroll 1
    for (int t = 0; t < 512; t++) {
        // ===== x-phase: Cx = x_t @ Wx (independent of barrier) =============
        float Cx[2][4];
#pragma unroll
        for (int i = 0; i < 2; i++)
#pragma unroll
            for (int q = 0; q < 4; q++) Cx[i][q] = 0.0f;
        st_phase(sb, WX_OFF, tid, lane, m_off, n_off,
                 g_xf + (size_t)t * 65536, Cx);

        // ===== barrier wait: h_t must be complete ==========================
        if (t > 0) {
            if (tid == 0) {
                while (ld_acq(&g_cnt[t - 1]) < NCTA) { }
            }
        }
        __syncthreads();   // also proves all warps done with x chunk c3 (s0)

        // ===== h-phase: Ch = h_t @ Wh ======================================
        float Ch[2][4];
#pragma unroll
        for (int i = 0; i < 2; i++)
#pragma unroll
            for (int q = 0; q < 4; q++) Ch[i][q] = 0.0f;
        st_phase(sb, WH_OFF, tid, lane, m_off, n_off, g_htf[t], Ch);

        // ===== merge frags -> Zs[n][b] (z = Ch + Cx + bias) ================
        // Zs overlays stage 1 (last read at chunk c1; two syncs ago).
        float* Zs = (float*)(sm + ZS_OFF);         // [32][66]
        {
#pragma unroll
            for (int mt = 0; mt < 2; mt++) {
                int m = m_off + mt * 16 + er;
                int n = n_off + ec2;
                Zs[n * 66 + m]           = Ch[mt][0] + Cx[mt][0] + bv0;
                Zs[(n + 1) * 66 + m]     = Ch[mt][1] + Cx[mt][1] + bv1;
                Zs[n * 66 + m + 8]       = Ch[mt][2] + Cx[mt][2] + bv0;
                Zs[(n + 1) * 66 + m + 8] = Ch[mt][3] + Cx[mt][3] + bv1;
            }
        }
        __syncthreads();

        // ===== fused gates; c in registers =================================
        {
            int b = tid >> 2, uq = tid & 3;
            float hv[2];
#pragma unroll
            for (int v = 0; v < 2; v++) {
                int uu = uq * 2 + v;
                float zi = Zs[uu * 66 + b];
                float zf = Zs[(8 + uu) * 66 + b];
                float zg = Zs[(16 + uu) * 66 + b];
                float zo = Zs[(24 + uu) * 66 + b];
                float ig = 1.0f / (1.0f + __expf(-zi));
                float fg = 1.0f / (1.0f + __expf(-zf));
                float gg = 2.0f / (1.0f + __expf(-2.0f * zg)) - 1.0f;
                float og = 1.0f / (1.0f + __expf(-zo));
                float cn = fg * creg[v] + ig * gg;
                creg[v] = cn;
                float th = 2.0f / (1.0f + __expf(-2.0f * cn)) - 1.0f;
                hv[v] = og * th;
            }
            *(float2*)&y[((size_t)b * 512 + t) * 1024 + j * 8 + uq * 2] =
                make_float2(hv[0], hv[1]);
            __half hf2[2];
            hf2[0] = __float2half_rn(hv[0]);
            hf2[1] = __float2half_rn(hv[1]);
            *(uint32_t*)(g_htf[t + 1] + (size_t)b * 1024 + j * 8 + uq * 2) = *(uint32_t*)hf2;
        }

        // ===== arrive: h_{t+1} visible -> release counter t ================
        __threadfence();
        __syncthreads();
        if (tid == 0) red_release(&g_cnt[t]);
    }
}

// ---------------------------------------------------------------------------
extern "C" void kernel_launch(void* const* d_in, const int* in_sizes, int n_in,
                              void* d_out, int out_size)
{
    const float* x  = (const float*)d_in[0];
    const float* Wx = (const float*)d_in[1];
    const float* Wh = (const float*)d_in[2];
    const float* b  = (const float*)d_in[3];
    float* y = (float*)d_out;

    cudaFuncSetAttribute(step_persist, cudaFuncAttributeMaxDynamicSharedMemorySize, ST_SMEM);

    init_kernel<<<64, 256>>>();
    pack_x_kernel<<<16384, 256>>>(x);
    pack_w_kernel<<<dim3(128, 32), 256>>>(Wx, 0);
    pack_w_kernel<<<dim3(128, 32), 256>>>(Wh, 1);
    step_persist<<<NCTA, 256, ST_SMEM>>>(y, b);
}